// round 2
// baseline (speedup 1.0000x reference)
#include <cuda_runtime.h>
#include <cuda_bf16.h>
#include <math.h>

// TemporalAttention: out[d,b] = sum_s softmax_s((enc[b,s,:]·We_w + We_b)*ut)[s] * enc[b,s,d]
// Single-pass online softmax, split over S, fused split-merge via last-CTA-done.
// enc_out read exactly once from HBM; MLP = 8 LDG.128 per warp iteration.

#define D_DIM    256
#define NSPLIT   16
#define WARPS    8
#define THREADS  (WARPS * 32)
#define MAXB     128

// Per-(b,split) partial: 256 acc values + m + l
__device__ float        g_scratch[MAXB * NSPLIT * (D_DIM + 2)];
__device__ unsigned int g_cnt[MAXB];   // zero-initialized; reset by merger each launch

__global__ __launch_bounds__(THREADS) void ta_fused(
    const float* __restrict__ enc,
    const float* __restrict__ Ww,
    const float* __restrict__ Wb,
    const float* __restrict__ ut,
    float* __restrict__ out,
    int S, int B)
{
    const int split = blockIdx.x;
    const int b     = blockIdx.y;
    const int w     = threadIdx.x >> 5;
    const int lane  = threadIdx.x & 31;

    // Per-lane slice of We_w (lane k owns d = 8k..8k+7)
    float wv[8];
#pragma unroll
    for (int j = 0; j < 8; j++) wv[j] = Ww[lane * 8 + j];
    const float be = Wb[0];
    const float u  = ut[0];

    const int s0   = (int)(((long long)split * S) / NSPLIT);
    const int s1   = (int)(((long long)(split + 1) * S) / NSPLIT);
    const int rows = s1 - s0;

    const float* base = enc + ((long long)b * S + s0) * D_DIM;

    float m = -1e30f;
    float l = 0.0f;
    float acc[8];
#pragma unroll
    for (int j = 0; j < 8; j++) acc[j] = 0.0f;

    // ---- main loop: 4 rows per warp per iteration -> 8 LDG.128 in flight ----
    int r = w;
    for (; r + 3 * WARPS < rows; r += 4 * WARPS) {
        const float4* p0 = (const float4*)(base + (long long)(r + 0 * WARPS) * D_DIM) + lane * 2;
        const float4* p1 = (const float4*)(base + (long long)(r + 1 * WARPS) * D_DIM) + lane * 2;
        const float4* p2 = (const float4*)(base + (long long)(r + 2 * WARPS) * D_DIM) + lane * 2;
        const float4* p3 = (const float4*)(base + (long long)(r + 3 * WARPS) * D_DIM) + lane * 2;
        float4 a0 = p0[0], a1 = p0[1];
        float4 b0 = p1[0], b1 = p1[1];
        float4 c0 = p2[0], c1 = p2[1];
        float4 d0 = p3[0], d1 = p3[1];

        float xA[8] = {a0.x, a0.y, a0.z, a0.w, a1.x, a1.y, a1.z, a1.w};
        float xB[8] = {b0.x, b0.y, b0.z, b0.w, b1.x, b1.y, b1.z, b1.w};
        float xC[8] = {c0.x, c0.y, c0.z, c0.w, c1.x, c1.y, c1.z, c1.w};
        float xD[8] = {d0.x, d0.y, d0.z, d0.w, d1.x, d1.y, d1.z, d1.w};

        float dA = 0.f, dB = 0.f, dC = 0.f, dD = 0.f;
#pragma unroll
        for (int j = 0; j < 8; j++) {
            dA = fmaf(xA[j], wv[j], dA);
            dB = fmaf(xB[j], wv[j], dB);
            dC = fmaf(xC[j], wv[j], dC);
            dD = fmaf(xD[j], wv[j], dD);
        }
        // 4 independent shuffle-reduction chains pipeline together
#pragma unroll
        for (int o = 16; o > 0; o >>= 1) {
            dA += __shfl_xor_sync(0xffffffffu, dA, o);
            dB += __shfl_xor_sync(0xffffffffu, dB, o);
            dC += __shfl_xor_sync(0xffffffffu, dC, o);
            dD += __shfl_xor_sync(0xffffffffu, dD, o);
        }
        float sA = (dA + be) * u;
        float sB = (dB + be) * u;
        float sC = (dC + be) * u;
        float sD = (dD + be) * u;

        float mnew = fmaxf(fmaxf(m, fmaxf(sA, sB)), fmaxf(sC, sD));
        float scale = __expf(m - mnew);
        float pA = __expf(sA - mnew);
        float pB = __expf(sB - mnew);
        float pC = __expf(sC - mnew);
        float pD = __expf(sD - mnew);
        l = l * scale + (pA + pB) + (pC + pD);
#pragma unroll
        for (int j = 0; j < 8; j++) {
            float t0 = fmaf(pA, xA[j], pB * xB[j]);
            float t1 = fmaf(pC, xC[j], pD * xD[j]);
            acc[j] = fmaf(acc[j], scale, t0 + t1);
        }
        m = mnew;
    }
    // ---- tail: one row at a time ----
    for (; r < rows; r += WARPS) {
        const float4* p0 = (const float4*)(base + (long long)r * D_DIM) + lane * 2;
        float4 a0 = p0[0], a1 = p0[1];
        float x[8] = {a0.x, a0.y, a0.z, a0.w, a1.x, a1.y, a1.z, a1.w};
        float d = 0.f;
#pragma unroll
        for (int j = 0; j < 8; j++) d = fmaf(x[j], wv[j], d);
#pragma unroll
        for (int o = 16; o > 0; o >>= 1) d += __shfl_xor_sync(0xffffffffu, d, o);
        float s = (d + be) * u;
        float mnew  = fmaxf(m, s);
        float scale = __expf(m - mnew);
        float p     = __expf(s - mnew);
        l = l * scale + p;
#pragma unroll
        for (int j = 0; j < 8; j++) acc[j] = fmaf(acc[j], scale, p * x[j]);
        m = mnew;
    }

    // ---- combine warps within the CTA ----
    __shared__ float s_acc[WARPS][D_DIM];
    __shared__ float s_m[WARPS], s_l[WARPS];
#pragma unroll
    for (int j = 0; j < 8; j++) s_acc[w][lane * 8 + j] = acc[j];
    if (lane == 0) { s_m[w] = m; s_l[w] = l; }
    __syncthreads();

    float M = -1e30f;
#pragma unroll
    for (int i = 0; i < WARPS; i++) M = fmaxf(M, s_m[i]);

    const int t = threadIdx.x;  // 0..255 == d index
    float a = 0.0f;
#pragma unroll
    for (int i = 0; i < WARPS; i++) a += __expf(s_m[i] - M) * s_acc[i][t];

    float* o = g_scratch + ((long long)(b * NSPLIT + split)) * (D_DIM + 2);
    o[t] = a;
    if (t == 0) {
        float L = 0.0f;
#pragma unroll
        for (int i = 0; i < WARPS; i++) L += __expf(s_m[i] - M) * s_l[i];
        o[D_DIM]     = M;
        o[D_DIM + 1] = L;
    }

    // ---- fused split-merge: last CTA per batch reduces all NSPLIT partials ----
    __threadfence();
    __syncthreads();
    __shared__ unsigned int s_last;
    if (t == 0) s_last = (atomicAdd(&g_cnt[b], 1u) == (unsigned)(NSPLIT - 1));
    __syncthreads();
    if (!s_last) return;

    const float* sc = g_scratch + (long long)b * NSPLIT * (D_DIM + 2);
    float Mg = -1e30f;
#pragma unroll
    for (int i = 0; i < NSPLIT; i++) Mg = fmaxf(Mg, sc[i * (D_DIM + 2) + D_DIM]);

    float Lg = 0.0f, ag = 0.0f;
#pragma unroll
    for (int i = 0; i < NSPLIT; i++) {
        float e = __expf(sc[i * (D_DIM + 2) + D_DIM] - Mg);
        Lg += e * sc[i * (D_DIM + 2) + D_DIM + 1];
        ag += e * sc[i * (D_DIM + 2) + t];
    }
    out[t * B + b] = ag / Lg;   // out is [D, B]

    if (t == 0) g_cnt[b] = 0;   // reset for next graph replay
}

extern "C" void kernel_launch(void* const* d_in, const int* in_sizes, int n_in,
                              void* d_out, int out_size)
{
    const float* enc = (const float*)d_in[0];
    const float* Ww  = (const float*)d_in[1];
    const float* Wb  = (const float*)d_in[2];
    const float* ut  = (const float*)d_in[3];
    float* out = (float*)d_out;

    const int D = in_sizes[1];           // 256
    const int B = out_size / D;          // 64
    const int S = in_sizes[0] / (B * D); // 4096

    dim3 grid(NSPLIT, B);
    ta_fused<<<grid, THREADS>>>(enc, Ww, Wb, ut, out, S, B);
}

// round 3
// speedup vs baseline: 1.0832x; 1.0832x over previous
#include <cuda_runtime.h>
#include <cuda_bf16.h>
#include <math.h>

// TemporalAttention: out[d,b] = sum_s softmax_s((enc[b,s,:]·We_w + We_b)*ut)[s] * enc[b,s,d]
// Single pass, no online max (scores bounded for fp32 exp), software-pipelined
// streaming loads (__ldcs), fused last-CTA-done split merge.

#define D_DIM    256
#define NSPLIT   8
#define WARPS    8
#define THREADS  (WARPS * 32)
#define MAXB     128

// Per-(b,split) partial: 256 acc values + l (+1 pad)
__device__ float        g_scratch[MAXB * NSPLIT * (D_DIM + 2)];
__device__ unsigned int g_cnt[MAXB];   // zero-init; reset by merger each launch

__global__ __launch_bounds__(THREADS, 4) void ta_fused(
    const float* __restrict__ enc,
    const float* __restrict__ Ww,
    const float* __restrict__ Wb,
    const float* __restrict__ ut,
    float* __restrict__ out,
    int S, int B)
{
    const int split = blockIdx.x;
    const int b     = blockIdx.y;
    const int w     = threadIdx.x >> 5;
    const int lane  = threadIdx.x & 31;

    // Per-lane slice of We_w (lane k owns d = 8k..8k+7)
    float wv[8];
#pragma unroll
    for (int j = 0; j < 8; j++) wv[j] = Ww[lane * 8 + j];
    const float be = Wb[0];
    const float u  = ut[0];

    const int s0   = (int)(((long long)split * S) / NSPLIT);
    const int s1   = (int)(((long long)(split + 1) * S) / NSPLIT);
    const int rows = s1 - s0;

    const float* base = enc + ((long long)b * S + s0) * D_DIM;

    float l = 0.0f;
    float acc[8];
#pragma unroll
    for (int j = 0; j < 8; j++) acc[j] = 0.0f;

#define LOADPAIR(v0, v1, v2, v3, ri)                                            \
    {                                                                           \
        const float4* _p0 = (const float4*)(base + (long long)(ri) * D_DIM) + lane * 2;          \
        const float4* _p1 = (const float4*)(base + (long long)((ri) + WARPS) * D_DIM) + lane * 2; \
        v0 = __ldcs(_p0); v1 = __ldcs(_p0 + 1);                                 \
        v2 = __ldcs(_p1); v3 = __ldcs(_p1 + 1);                                 \
    }

#define PROCESS(v0, v1, v2, v3)                                                 \
    {                                                                           \
        float xA[8] = {v0.x, v0.y, v0.z, v0.w, v1.x, v1.y, v1.z, v1.w};         \
        float xB[8] = {v2.x, v2.y, v2.z, v2.w, v3.x, v3.y, v3.z, v3.w};         \
        float dA = 0.f, dB = 0.f;                                               \
        _Pragma("unroll")                                                       \
        for (int j = 0; j < 8; j++) {                                           \
            dA = fmaf(xA[j], wv[j], dA);                                        \
            dB = fmaf(xB[j], wv[j], dB);                                        \
        }                                                                       \
        _Pragma("unroll")                                                       \
        for (int o = 16; o > 0; o >>= 1) {                                      \
            dA += __shfl_xor_sync(0xffffffffu, dA, o);                          \
            dB += __shfl_xor_sync(0xffffffffu, dB, o);                          \
        }                                                                       \
        float pA = __expf((dA + be) * u);                                       \
        float pB = __expf((dB + be) * u);                                       \
        l += pA + pB;                                                           \
        _Pragma("unroll")                                                       \
        for (int j = 0; j < 8; j++)                                             \
            acc[j] = fmaf(pA, xA[j], fmaf(pB, xB[j], acc[j]));                  \
    }

    int r = w;
    if (r + WARPS < rows) {
        float4 c0, c1, c2, c3;
        LOADPAIR(c0, c1, c2, c3, r);
        int rn = r + 2 * WARPS;
        while (rn + WARPS < rows) {
            float4 n0, n1, n2, n3;
            LOADPAIR(n0, n1, n2, n3, rn);   // prefetch next pair
            PROCESS(c0, c1, c2, c3);        // process current (loads in flight)
            c0 = n0; c1 = n1; c2 = n2; c3 = n3;
            rn += 2 * WARPS;
        }
        PROCESS(c0, c1, c2, c3);
        r = rn;
    }
    // tail: single rows
    for (; r < rows; r += WARPS) {
        const float4* p0 = (const float4*)(base + (long long)r * D_DIM) + lane * 2;
        float4 a0 = __ldcs(p0), a1 = __ldcs(p0 + 1);
        float x[8] = {a0.x, a0.y, a0.z, a0.w, a1.x, a1.y, a1.z, a1.w};
        float d = 0.f;
#pragma unroll
        for (int j = 0; j < 8; j++) d = fmaf(x[j], wv[j], d);
#pragma unroll
        for (int o = 16; o > 0; o >>= 1) d += __shfl_xor_sync(0xffffffffu, d, o);
        float p = __expf((d + be) * u);
        l += p;
#pragma unroll
        for (int j = 0; j < 8; j++) acc[j] = fmaf(p, x[j], acc[j]);
    }

    // ---- combine warps within the CTA (plain sums, no rescale) ----
    __shared__ float s_acc[WARPS][D_DIM];
    __shared__ float s_l[WARPS];
#pragma unroll
    for (int j = 0; j < 8; j++) s_acc[w][lane * 8 + j] = acc[j];
    if (lane == 0) s_l[w] = l;
    __syncthreads();

    const int t = threadIdx.x;  // 0..255 == d index
    float a = 0.0f;
#pragma unroll
    for (int i = 0; i < WARPS; i++) a += s_acc[i][t];

    float* o = g_scratch + ((long long)(b * NSPLIT + split)) * (D_DIM + 2);
    o[t] = a;
    if (t == 0) {
        float L = 0.0f;
#pragma unroll
        for (int i = 0; i < WARPS; i++) L += s_l[i];
        o[D_DIM] = L;
    }

    // ---- fused split-merge: last CTA per batch sums all NSPLIT partials ----
    __threadfence();
    __syncthreads();
    __shared__ unsigned int s_last;
    if (t == 0) s_last = (atomicAdd(&g_cnt[b], 1u) == (unsigned)(NSPLIT - 1));
    __syncthreads();
    if (!s_last) return;

    const float* sc = g_scratch + (long long)b * NSPLIT * (D_DIM + 2);
    float Lg = 0.0f, ag = 0.0f;
#pragma unroll
    for (int i = 0; i < NSPLIT; i++) {
        Lg += sc[i * (D_DIM + 2) + D_DIM];
        ag += sc[i * (D_DIM + 2) + t];
    }
    out[t * B + b] = ag / Lg;   // out is [D, B]

    if (t == 0) g_cnt[b] = 0;   // reset for next graph replay
}

extern "C" void kernel_launch(void* const* d_in, const int* in_sizes, int n_in,
                              void* d_out, int out_size)
{
    const float* enc = (const float*)d_in[0];
    const float* Ww  = (const float*)d_in[1];
    const float* Wb  = (const float*)d_in[2];
    const float* ut  = (const float*)d_in[3];
    float* out = (float*)d_out;

    const int D = in_sizes[1];           // 256
    const int B = out_size / D;          // 64
    const int S = in_sizes[0] / (B * D); // 4096

    dim3 grid(NSPLIT, B);
    ta_fused<<<grid, THREADS>>>(enc, Ww, Wb, ut, out, S, B);
}